// round 15
// baseline (speedup 1.0000x reference)
#include <cuda_runtime.h>

// SSIM loss, fused separable 11x11 gaussian blur + ssim map + mean reduce.
// R15 = R14 (190.8us; NT=512, 4 CTAs, occ 92%, issue 81%) + 2 instr cuts:
//  (1) field planes store pairs {B(x),B(x^2)} per pixel -> P3 does 2xLDS.64
//      per tap instead of 4xLDS.32 (26 vs 52 loads/thread; wavefronts halve).
//      Lane-consecutive float2/float4 -> conflict-free (unlike R8's stride-6).
//  (2) TH 22->24 (INH=34): P3 = 8 groups x exactly 3 rows (clamp deleted),
//      outputs/block +9%. smem 55.5KB x4 = 217KB fits; reg shape unchanged.
// Model: per-output instr 182 -> ~165 at same occupancy.

#define IMG      512
#define TW       64
#define TH       24
#define HALO     5
#define INW      74          // TW + 2*HALO
#define INWP     76          // padded row stride
#define INH      34          // TH + 2*HALO
#define NT       512
#define PPLANE   (INH * 128) // paired plane: [INH][64][2] floats

#define GX       8           // 512/64
#define GY       22          // 22*24 = 528 rows, tail masked
#define PL       96
#define NB       (GX * GY * PL)   // 16896 = 33*512

#define SMEM_FLOATS (2 * INH * INWP + 2 * PPLANE)   // 5168 + 8704 = 13872
#define SMEM_BYTES  (SMEM_FLOATS * 4)               // 55488

__device__ float g_part[NB];
__device__ float g_part2[33];

// 1D gaussian, sigma=1.5, K=11, normalized. Constant indices fold to
// FFMA immediates (rt_SMSP=1 imm-form).
__device__ __forceinline__ constexpr float gw(int k) {
    switch (k) {
        case 0:  return 0.00102838f;
        case 1:  return 0.00759877f;
        case 2:  return 0.03600077f;
        case 3:  return 0.10936069f;
        case 4:  return 0.21300554f;
        case 5:  return 0.26601173f;
        case 6:  return 0.21300554f;
        case 7:  return 0.10936069f;
        case 8:  return 0.03600077f;
        case 9:  return 0.00759877f;
        case 10: return 0.00102838f;
    }
    return 0.0f;
}

// One half of the horizontal blur: 16-float window -> {B(x), B(x^2)} for
// 4 cols, stored PAIRED: dst[row*128 + 2j] = {f[j], f2[j]}.
__device__ __forceinline__ void hblur_half(const float* __restrict__ src,
                                           float* __restrict__ dst,
                                           int row, int c0) {
    float a[16];
    {
        const float4* a4 = (const float4*)(src + row * INWP + c0);
        ((float4*)a)[0] = a4[0]; ((float4*)a)[1] = a4[1];
        ((float4*)a)[2] = a4[2]; ((float4*)a)[3] = a4[3];
    }
    float f[4]  = {0.f, 0.f, 0.f, 0.f};
    float f2[4] = {0.f, 0.f, 0.f, 0.f};
    #pragma unroll
    for (int i = 0; i < 14; i++) {
        float v = a[i];
        float vv = v * v;
        #pragma unroll
        for (int j = 0; j < 4; j++) {
            int k = i - j;
            if (k >= 0 && k < 11) {
                float w = gw(k);
                f[j]  = fmaf(v,  w, f[j]);
                f2[j] = fmaf(vv, w, f2[j]);
            }
        }
    }
    float* h = dst + row * 128 + 2 * c0;
    *(float4*)(h + 0) = make_float4(f[0], f2[0], f[1], f2[1]);
    *(float4*)(h + 4) = make_float4(f[2], f2[2], f[3], f2[3]);
}

__global__ __launch_bounds__(NT, 4)
void ssim_main(const float* __restrict__ img1, const float* __restrict__ img2) {
    extern __shared__ float smem[];
    float* ss  = smem;                      // s = x1+x2 tile [INH][INWP]
    float* sd  = smem + INH * INWP;         // d = x1-x2 tile
    float* shA = smem + 2 * INH * INWP;     // paired {Bs,Bs2} [INH][64][2]
    float* shB = shA + PPLANE;              // paired {Bd,Bd2}
    __shared__ float wsum[NT / 32];

    const int tid = threadIdx.x;
    const int gx0 = blockIdx.x * TW - HALO;
    const int gy0 = blockIdx.y * TH - HALO;
    const size_t pbase = (size_t)blockIdx.z * (IMG * IMG);
    const float* p1 = img1 + pbase;
    const float* p2 = img2 + pbase;

    // ---- Phase 1: global -> smem. s=(i1+i2)*0.5+1, d=(i1-i2)*0.5. ----
    {   // rows 0..31: thread (r = tid>>4, c = tid&15) covers cols c+16k
        const int r  = tid >> 4;
        const int c  = tid & 15;
        const int gy = gy0 + r;
        const bool rowok = (gy >= 0) && (gy < IMG);
        const float* q1 = p1 + (ptrdiff_t)gy * IMG;
        const float* q2 = p2 + (ptrdiff_t)gy * IMG;
        #pragma unroll
        for (int k = 0; k < 5; k++) {
            int cc = c + 16 * k;
            if (k < 4 || cc < INWP) {
                int gx = gx0 + cc;
                float vs = 0.f, vd = 0.f;
                if (rowok && cc < INW && gx >= 0 && gx < IMG) {
                    float a = q1[gx], b = q2[gx];
                    vs = fmaf(a + b, 0.5f, 1.0f);
                    vd = (a - b) * 0.5f;
                }
                ss[r * INWP + cc] = vs;
                sd[r * INWP + cc] = vd;
            }
        }
    }
    if (tid < 256) {   // rows 32,33: one element per thread
        const int r  = 32 + (tid >> 7);
        const int cc = tid & 127;
        if (cc < INWP) {
            const int gy = gy0 + r;
            const bool rowok = (gy >= 0) && (gy < IMG);
            int gx = gx0 + cc;
            float vs = 0.f, vd = 0.f;
            if (rowok && cc < INW && gx >= 0 && gx < IMG) {
                float a = p1[(ptrdiff_t)gy * IMG + gx];
                float b = p2[(ptrdiff_t)gy * IMG + gx];
                vs = fmaf(a + b, 0.5f, 1.0f);
                vd = (a - b) * 0.5f;
            }
            ss[r * INWP + cc] = vs;
            sd[r * INWP + cc] = vd;
        }
    }
    __syncthreads();

    // ---- Phase 2: horizontal blur. 544 tasks: main 512 + residual 32 ----
    {
        const int row = tid >> 4;           // 0..31
        const int c0  = (tid & 15) << 2;    // 0,4,...,60
        hblur_half(ss, shA, row, c0);       // s half -> {Bs,Bs2}
        hblur_half(sd, shB, row, c0);       // d half -> {Bd,Bd2}
    }
    if (tid < 32) {                         // rows 32,33
        const int row = 32 + (tid >> 4);
        const int c0  = (tid & 15) << 2;
        hblur_half(ss, shA, row, c0);
        hblur_half(sd, shB, row, c0);
    }
    __syncthreads();

    // ---- Phase 3: vertical blur + ssim. 64 cols x 8 groups x 3 rows ----
    const int col = tid & 63;
    const int g   = tid >> 6;               // 0..7
    const int r_start = 3 * g;              // 0..21; taps reach 21+12=33=INH-1

    float aS[3], aS2[3], aD[3], aD2[3];
    #pragma unroll
    for (int j = 0; j < 3; j++) {
        aS[j] = 0.f; aS2[j] = 0.f; aD[j] = 0.f; aD2[j] = 0.f;
    }

    #pragma unroll
    for (int i = 0; i < 13; i++) {
        const float* pa = shA + (r_start + i) * 128 + 2 * col;
        float2 ha = *(const float2*)pa;             // {Bs, Bs2} contrib
        float2 hb = *(const float2*)(pa + PPLANE);  // {Bd, Bd2} contrib
        #pragma unroll
        for (int j = 0; j < 3; j++) {
            int k = i - j;
            if (k >= 0 && k < 11) {
                float w = gw(k);
                aS[j]  = fmaf(ha.x, w, aS[j]);
                aS2[j] = fmaf(ha.y, w, aS2[j]);
                aD[j]  = fmaf(hb.x, w, aD[j]);
                aD2[j] = fmaf(hb.y, w, aD2[j]);
            }
        }
    }

    const float C1 = 0.0001f;   // 0.01^2
    const float C2 = 0.0009f;   // 0.03^2
    const int   gyb = blockIdx.y * TH + r_start;
    float tsum = 0.f;
    #pragma unroll
    for (int j = 0; j < 3; j++) {
        if (gyb + j < IMG) {
            float Bs  = aS[j],  Bd  = aD[j];
            float Bs2 = aS2[j], Bd2 = aD2[j];
            float bss = Bs * Bs, bdd = Bd * Bd;
            float mu12   = 0.25f * (bss - bdd);        // mu1*mu2
            float musq   = 0.50f * (bss + bdd);        // mu1^2 + mu2^2
            float sig12  = 0.25f * (Bs2 - Bd2) - mu12; // sigma12
            float sigsum = 0.50f * (Bs2 + Bd2) - musq; // sig1^2 + sig2^2
            float num = fmaf(2.f, mu12,  C1) * fmaf(2.f, sig12, C2);
            float den = (musq + C1) * (sigsum + C2);
            tsum += __fdividef(num, den);
        }
    }

    // ---- Reduction: warp shuffle -> static wsum (1 barrier) -> STG ----
    #pragma unroll
    for (int off = 16; off; off >>= 1)
        tsum += __shfl_xor_sync(0xffffffffu, tsum, off);

    if ((tid & 31) == 0) wsum[tid >> 5] = tsum;
    __syncthreads();
    if (tid == 0) {
        float bs = 0.f;
        #pragma unroll
        for (int i = 0; i < NT / 32; i++) bs += wsum[i];
        int slot = (blockIdx.z * GY + blockIdx.y) * GX + blockIdx.x;
        g_part[slot] = bs;
    }
}

__global__ __launch_bounds__(512)
void ssim_reduce1() {
    __shared__ float ws[16];
    const int tid = threadIdx.x;
    float s = g_part[blockIdx.x * 512 + tid];

    #pragma unroll
    for (int off = 16; off; off >>= 1)
        s += __shfl_xor_sync(0xffffffffu, s, off);
    if ((tid & 31) == 0) ws[tid >> 5] = s;
    __syncthreads();
    if (tid < 32) {
        float t = (tid < 16) ? ws[tid] : 0.f;
        #pragma unroll
        for (int off = 16; off; off >>= 1)
            t += __shfl_xor_sync(0xffffffffu, t, off);
        if (tid == 0) g_part2[blockIdx.x] = t;
    }
}

__global__ void ssim_fin(float* out, double inv_n) {
    const int tid = threadIdx.x;   // 32 threads
    double s = (double)g_part2[tid];
    if (tid == 0) s += (double)g_part2[32];
    #pragma unroll
    for (int off = 16; off; off >>= 1)
        s += __shfl_xor_sync(0xffffffffu, s, off);
    if (tid == 0) out[0] = 1.0f - (float)(s * inv_n);
}

extern "C" void kernel_launch(void* const* d_in, const int* in_sizes, int n_in,
                              void* d_out, int out_size) {
    const float* img1 = (const float*)d_in[0];
    const float* img2 = (const float*)d_in[1];
    (void)n_in; (void)out_size; (void)in_sizes;

    cudaFuncSetAttribute(ssim_main, cudaFuncAttributeMaxDynamicSharedMemorySize,
                         SMEM_BYTES);

    dim3 grid(GX, GY, PL);
    ssim_main<<<grid, NT, SMEM_BYTES>>>(img1, img2);

    ssim_reduce1<<<33, 512>>>();
    double inv_n = 1.0 / ((double)PL * IMG * IMG);
    ssim_fin<<<1, 32>>>((float*)d_out, inv_n);
}

// round 16
// speedup vs baseline: 1.0118x; 1.0118x over previous
#include <cuda_runtime.h>

// SSIM loss, fused separable 11x11 gaussian blur + ssim map + mean reduce.
// R16 = R14 (190.8us best: NT=512, 4 CTAs, TH=22, occ 92%, issue 81%) plus
// ONLY the paired-field-store change from R15 (R15 bundled it with TH=24
// residual passes whose tail imbalance ate the gain: issue 81->73.6):
// field planes hold {B(x),B(x^2)} pairs -> P3 does 26 LDS.64 instead of
// 52 LDS.32. Same smem (52224B), same balanced 512-task phases, regs 32.

#define IMG      512
#define TW       64
#define TH       22
#define HALO     5
#define INW      74          // TW + 2*HALO
#define INWP     76          // padded row stride
#define INH      32          // TH + 2*HALO
#define NT       512
#define PPLANE   (INH * 128) // paired plane: [INH][64][2] floats = 4096

#define GX       8           // 512/64
#define GY       24          // 24*22 = 528 rows, tail masked
#define PL       96
#define NB       (GX * GY * PL)   // 18432 = 18*1024

#define SMEM_FLOATS (2 * INH * INWP + 2 * PPLANE)   // 4864 + 8192 = 13056
#define SMEM_BYTES  (SMEM_FLOATS * 4)               // 52224

__device__ float g_part[NB];
__device__ float g_part2[18];

// 1D gaussian, sigma=1.5, K=11, normalized. Constant indices fold to
// FFMA immediates (rt_SMSP=1 imm-form).
__device__ __forceinline__ constexpr float gw(int k) {
    switch (k) {
        case 0:  return 0.00102838f;
        case 1:  return 0.00759877f;
        case 2:  return 0.03600077f;
        case 3:  return 0.10936069f;
        case 4:  return 0.21300554f;
        case 5:  return 0.26601173f;
        case 6:  return 0.21300554f;
        case 7:  return 0.10936069f;
        case 8:  return 0.03600077f;
        case 9:  return 0.00759877f;
        case 10: return 0.00102838f;
    }
    return 0.0f;
}

// One half of the horizontal blur: 16-float window -> {B(x), B(x^2)} for
// 4 cols, stored PAIRED: dst[row*128 + 2j] = {f[j], f2[j]}.
__device__ __forceinline__ void hblur_half(const float* __restrict__ src,
                                           float* __restrict__ dst,
                                           int row, int c0) {
    float a[16];
    {
        const float4* a4 = (const float4*)(src + row * INWP + c0);
        ((float4*)a)[0] = a4[0]; ((float4*)a)[1] = a4[1];
        ((float4*)a)[2] = a4[2]; ((float4*)a)[3] = a4[3];
    }
    float f[4]  = {0.f, 0.f, 0.f, 0.f};
    float f2[4] = {0.f, 0.f, 0.f, 0.f};
    #pragma unroll
    for (int i = 0; i < 14; i++) {
        float v = a[i];
        float vv = v * v;
        #pragma unroll
        for (int j = 0; j < 4; j++) {
            int k = i - j;
            if (k >= 0 && k < 11) {
                float w = gw(k);
                f[j]  = fmaf(v,  w, f[j]);
                f2[j] = fmaf(vv, w, f2[j]);
            }
        }
    }
    float* h = dst + row * 128 + 2 * c0;
    *(float4*)(h + 0) = make_float4(f[0], f2[0], f[1], f2[1]);
    *(float4*)(h + 4) = make_float4(f[2], f2[2], f[3], f2[3]);
}

__global__ __launch_bounds__(NT, 4)
void ssim_main(const float* __restrict__ img1, const float* __restrict__ img2) {
    extern __shared__ float smem[];
    float* ss  = smem;                      // s = x1+x2 tile [INH][INWP]
    float* sd  = smem + INH * INWP;         // d = x1-x2 tile
    float* shA = smem + 2 * INH * INWP;     // paired {Bs,Bs2} [INH][64][2]
    float* shB = shA + PPLANE;              // paired {Bd,Bd2}
    __shared__ float wsum[NT / 32];

    const int tid = threadIdx.x;
    const int gx0 = blockIdx.x * TW - HALO;
    const int gy0 = blockIdx.y * TH - HALO;
    const size_t pbase = (size_t)blockIdx.z * (IMG * IMG);
    const float* p1 = img1 + pbase;
    const float* p2 = img2 + pbase;

    // ---- Phase 1: global -> smem. s=(i1+i2)*0.5+1, d=(i1-i2)*0.5.
    //      thread (r = tid>>4, c = tid&15) covers cols c+16k, 5 iters. ----
    {
        const int r  = tid >> 4;
        const int c  = tid & 15;
        const int gy = gy0 + r;
        const bool rowok = (gy >= 0) && (gy < IMG);
        const float* q1 = p1 + (ptrdiff_t)gy * IMG;
        const float* q2 = p2 + (ptrdiff_t)gy * IMG;
        #pragma unroll
        for (int k = 0; k < 5; k++) {
            int cc = c + 16 * k;
            if (k < 4 || cc < INWP) {
                int gx = gx0 + cc;
                float vs = 0.f, vd = 0.f;
                if (rowok && cc < INW && gx >= 0 && gx < IMG) {
                    float a = q1[gx], b = q2[gx];
                    vs = fmaf(a + b, 0.5f, 1.0f);
                    vd = (a - b) * 0.5f;
                }
                ss[r * INWP + cc] = vs;
                sd[r * INWP + cc] = vd;
            }
        }
    }
    __syncthreads();

    // ---- Phase 2: horizontal blur, 4 output cols/thread, 512 tasks ----
    {
        const int row = tid >> 4;           // 0..31
        const int c0  = (tid & 15) << 2;    // 0,4,...,60
        hblur_half(ss, shA, row, c0);       // s half -> {Bs,Bs2}
        hblur_half(sd, shB, row, c0);       // d half -> {Bd,Bd2}
    }
    __syncthreads();

    // ---- Phase 3: vertical blur + ssim. 64 cols x 8 groups
    //      (rows 3,3,3,3,3,3,2,2), paired float2 loads ----
    const int col = tid & 63;
    const int g   = tid >> 6;               // 0..7
    const int r_start = (g < 6) ? 3 * g : 18 + 2 * (g - 6);
    const int nrows   = (g < 6) ? 3 : 2;

    float aS[3], aS2[3], aD[3], aD2[3];
    #pragma unroll
    for (int j = 0; j < 3; j++) {
        aS[j] = 0.f; aS2[j] = 0.f; aD[j] = 0.f; aD2[j] = 0.f;
    }

    #pragma unroll
    for (int i = 0; i < 13; i++) {
        int ri = r_start + i;
        if (ri > INH - 1) ri = INH - 1;      // clamp feeds only masked outputs
        const float* pa = shA + ri * 128 + 2 * col;
        float2 ha = *(const float2*)pa;             // {Bs, Bs2} contrib
        float2 hb = *(const float2*)(pa + PPLANE);  // {Bd, Bd2} contrib
        #pragma unroll
        for (int j = 0; j < 3; j++) {
            int k = i - j;
            if (k >= 0 && k < 11) {
                float w = gw(k);
                aS[j]  = fmaf(ha.x, w, aS[j]);
                aS2[j] = fmaf(ha.y, w, aS2[j]);
                aD[j]  = fmaf(hb.x, w, aD[j]);
                aD2[j] = fmaf(hb.y, w, aD2[j]);
            }
        }
    }

    const float C1 = 0.0001f;   // 0.01^2
    const float C2 = 0.0009f;   // 0.03^2
    const int   gyb = blockIdx.y * TH + r_start;
    float tsum = 0.f;
    #pragma unroll
    for (int j = 0; j < 3; j++) {
        bool valid = (j < nrows) && (gyb + j < IMG);
        if (valid) {
            float Bs  = aS[j],  Bd  = aD[j];
            float Bs2 = aS2[j], Bd2 = aD2[j];
            float bss = Bs * Bs, bdd = Bd * Bd;
            float mu12   = 0.25f * (bss - bdd);        // mu1*mu2
            float musq   = 0.50f * (bss + bdd);        // mu1^2 + mu2^2
            float sig12  = 0.25f * (Bs2 - Bd2) - mu12; // sigma12
            float sigsum = 0.50f * (Bs2 + Bd2) - musq; // sig1^2 + sig2^2
            float num = fmaf(2.f, mu12,  C1) * fmaf(2.f, sig12, C2);
            float den = (musq + C1) * (sigsum + C2);
            tsum += __fdividef(num, den);
        }
    }

    // ---- Reduction: warp shuffle -> static wsum (1 barrier) -> STG ----
    #pragma unroll
    for (int off = 16; off; off >>= 1)
        tsum += __shfl_xor_sync(0xffffffffu, tsum, off);

    if ((tid & 31) == 0) wsum[tid >> 5] = tsum;
    __syncthreads();
    if (tid == 0) {
        float bs = 0.f;
        #pragma unroll
        for (int i = 0; i < NT / 32; i++) bs += wsum[i];
        int slot = (blockIdx.z * GY + blockIdx.y) * GX + blockIdx.x;
        g_part[slot] = bs;
    }
}

__global__ __launch_bounds__(1024)
void ssim_reduce1() {
    __shared__ float ws[32];
    const int tid = threadIdx.x;
    float s = g_part[blockIdx.x * 1024 + tid];

    #pragma unroll
    for (int off = 16; off; off >>= 1)
        s += __shfl_xor_sync(0xffffffffu, s, off);
    if ((tid & 31) == 0) ws[tid >> 5] = s;
    __syncthreads();
    if (tid < 32) {
        float t = ws[tid];
        #pragma unroll
        for (int off = 16; off; off >>= 1)
            t += __shfl_xor_sync(0xffffffffu, t, off);
        if (tid == 0) g_part2[blockIdx.x] = t;
    }
}

__global__ void ssim_fin(float* out, double inv_n) {
    const int tid = threadIdx.x;   // 32 threads
    double s = (tid < 18) ? (double)g_part2[tid] : 0.0;
    #pragma unroll
    for (int off = 16; off; off >>= 1)
        s += __shfl_xor_sync(0xffffffffu, s, off);
    if (tid == 0) out[0] = 1.0f - (float)(s * inv_n);
}

extern "C" void kernel_launch(void* const* d_in, const int* in_sizes, int n_in,
                              void* d_out, int out_size) {
    const float* img1 = (const float*)d_in[0];
    const float* img2 = (const float*)d_in[1];
    (void)n_in; (void)out_size; (void)in_sizes;

    cudaFuncSetAttribute(ssim_main, cudaFuncAttributeMaxDynamicSharedMemorySize,
                         SMEM_BYTES);

    dim3 grid(GX, GY, PL);
    ssim_main<<<grid, NT, SMEM_BYTES>>>(img1, img2);

    ssim_reduce1<<<18, 1024>>>();
    double inv_n = 1.0 / ((double)PL * IMG * IMG);
    ssim_fin<<<1, 32>>>((float*)d_out, inv_n);
}